// round 4
// baseline (speedup 1.0000x reference)
#include <cuda_runtime.h>
#include <math.h>

// ---------------------------------------------------------------------------
// AcousticGuitarPoC: fused (params + pre-LP + doubled Karplus-Strong +
// post-LP) -> bodyAB (chunk states + carry scan) -> bodyC (recompute + mix).
// B=8, N=32768. 3 kernel launches.
// ---------------------------------------------------------------------------

#define FS_F   44100.0f
#define PI_F   3.14159265358979323846f
#define NB     24
#define NSMP   32768
#define BATCH  8
#define NTH    256      // fused-kernel threads
#define LCH    128      // LP chunk length (256*128 = 32768)
#define KSL    1024     // KS ring (power of 2)
#define BL     128      // body chunk length
#define BC     256      // body chunk count (256*128 = 32768)
#define NLVL   8        // log2(BC) scan levels

__device__ float  d_bA1[NB], d_bA2[NB], d_bB0[NB];
__device__ float  d_Pl[NB][NLVL][4];          // M^(BL*2^j), double-computed
__device__ float  d_scr[BATCH * NSMP];        // string output for body stage
__device__ float2 d_initS[BATCH][BC][NB];     // body corrected chunk init states

__device__ __forceinline__ float sigm(float x) { return 1.f / (1.f + expf(-x)); }
__device__ __forceinline__ float clampf(float x, float lo, float hi) {
    return fminf(fmaxf(x, lo), hi);
}

__device__ __forceinline__ void mlp_eval(float p,
    const float* __restrict__ w1, const float* __restrict__ b1,
    const float* __restrict__ w2, const float* __restrict__ b2,
    float& lc, float& lm, float& lp)
{
    float m0 = b2[0], m1 = b2[1], m2 = b2[2];
    #pragma unroll
    for (int j = 0; j < 16; j++) {
        float h = fmaxf(fmaf(p, w1[j], b1[j]), 0.f);
        m0 = fmaf(h, w2[j],      m0);
        m1 = fmaf(h, w2[16 + j], m1);
        m2 = fmaf(h, w2[32 + j], m2);
    }
    lc = clampf(m0, -2.0f, 2.5f);
    lm = clampf(m1, -2.5f, 0.0f);
    lp = clampf(m2, -4.0f, 4.0f);
}

// In-place one-pole LP: y[n] = m*y[n-1] + sc*x[n]; chunked + carry scan.
__device__ void lp_inplace(float* sig, float* scanbuf, float m, float sc, int tid)
{
    float* x = sig + tid * LCH;

    float e = 0.f;
    #pragma unroll 8
    for (int k = 0; k < LCH; k++) e = fmaf(m, e, sc * x[k]);

    scanbuf[tid] = e;
    __syncthreads();

    float f = m;
    #pragma unroll
    for (int i = 0; i < 7; i++) f *= f;       // m^128

    #pragma unroll
    for (int ofs = 1; ofs < NTH; ofs <<= 1) {
        float v = (tid >= ofs) ? scanbuf[tid - ofs] : 0.f;
        __syncthreads();
        e = fmaf(f, v, e);
        scanbuf[tid] = e;
        f *= f;
        __syncthreads();
    }

    float yp = (tid > 0) ? scanbuf[tid - 1] : 0.f;
    #pragma unroll 8
    for (int k = 0; k < LCH; k++) { yp = fmaf(m, yp, sc * x[k]); x[k] = yp; }
    __syncthreads();
}

// Pre-pass: sig <- (1 + C + ... + C^(2^L-1)) sig, in place. Pure function of
// the ORIGINAL sig: backward chunk order + two-phase (read/bar/write) keeps
// originals visible (chunk k's writes [base,base+256) are disjoint from all
// later-processed chunks' reads, which target < base). 1 barrier per chunk.
template<int NT>
__device__ __forceinline__ void ks_prepass(float* sig,
    const float* __restrict__ coefs, const int* __restrict__ offs, int tid)
{
    float cr[NT]; int of[NT];
    #pragma unroll
    for (int j = 0; j < NT; j++) { cr[j] = coefs[j]; of[j] = offs[j]; }
    for (int base = NSMP - NTH; base >= 0; base -= NTH) {
        int n = base + tid;
        float r[NT];
        #pragma unroll
        for (int j = 0; j < NT; j++) {
            int idx = n - of[j];
            r[j] = (idx >= 0) ? sig[idx] : 0.f;
        }
        float acc = sig[n];
        __syncthreads();
        #pragma unroll
        for (int j = 0; j < NT; j++) acc = fmaf(cr[j], r[j], acc);
        sig[n] = acc;
    }
    __syncthreads();
}

// Serial loop: y[n] = x[n] + sum_j coef[j]*y[n - lagbase - j], lagbase >= Cb.
// One barrier per chunk; ring aliasing safe (lagmax + Cb <= 993 < KSL).
template<int NT>
__device__ __forceinline__ void ks_serial(float* sig, float* buf,
    const float* __restrict__ coefs, int lagbase, int Cb, int tid)
{
    float cr[NT];
    #pragma unroll
    for (int j = 0; j < NT; j++) cr[j] = coefs[j];
    int nchunks = (NSMP + Cb - 1) / Cb;
    int base = 0;
    for (int k = 0; k < nchunks; k++, base += Cb) {
        int n = base + tid;
        if (tid < Cb && n < NSMP) {
            int p = n - lagbase;
            float r[NT];
            #pragma unroll
            for (int j = 0; j < NT; j++) r[j] = buf[(p - j) & (KSL - 1)];
            float acc = sig[n];
            #pragma unroll
            for (int j = 0; j < NT; j++) acc = fmaf(cr[j], r[j], acc);
            buf[n & (KSL - 1)] = acc;
            sig[n] = acc;
        }
        __syncthreads();
    }
}

// ---------------------------------------------------------------------------
// Fused kernel: one block per batch.
// ---------------------------------------------------------------------------
__global__ void fused_kernel(const float* __restrict__ exc,
                             const float* __restrict__ pitch,
                             const float* __restrict__ w1,
                             const float* __restrict__ b1,
                             const float* __restrict__ w2,
                             const float* __restrict__ b2,
                             const float* __restrict__ egain,
                             float* out_tail, int write_scalars)
{
    extern __shared__ float sm[];
    float* sig  = sm;              // [NSMP]
    float* buf  = sm + NSMP;       // [KSL]
    float* scan = buf + KSL;       // [NTH]

    __shared__ float s_mpre, s_scpre, s_mpost, s_scpost;
    __shared__ float s_ser[9], s_pc[15];
    __shared__ int   s_po[15], s_nser, s_npre, s_lagbase, s_Cb;
    __shared__ float s_lc[BATCH], s_lm[BATCH], s_lp[BATCH];

    int b = blockIdx.x, tid = threadIdx.x;

    if (tid == 0) {
        float p = pitch[b];
        float lc, lm, lp;
        mlp_eval(p, w1, b1, w2, b2, lc, lm, lp);

        float g = 0.999f * sigm(lc);
        float s = sigm(lm);
        float gs  = g * s;
        float g1s = g * (1.f - s);

        float f0    = fmaxf(p, 60.f);
        float mult  = clampf(2.f + 6.f * (f0 - 60.f) / 600.f, 2.f, 8.f);
        float cut   = fminf(2.f * PI_F * f0 * mult / FS_F, PI_F * 0.9f);
        float alpha = 1.f - expf(-cut);
        s_mpre  = 1.f - alpha;
        s_scpre = alpha * egain[0];

        float cutp = fminf(PI_F * sigm(lp), PI_F * 0.99f);
        float ap   = 1.f - expf(-cutp);
        s_mpost  = 1.f - ap;
        s_scpost = ap;

        float D  = clampf(FS_F / f0, 2.f, 735.f);
        float Df = floorf(D);
        int   Di = (int)Df;
        float fr = D - Df;

        // 3-tap loop filter: y[n] = x[n] + c1 y[n-Di] + c2 y[n-Di-1] + c3 y[n-Di-2]
        float t1[3], t2[5], t3[7], t4[9];
        t1[0] = g1s * (1.f - fr);
        t1[1] = g1s * fr + gs * (1.f - fr);
        t1[2] = gs * fr;
        for (int k = 0; k < 5; k++) t2[k] = 0.f;
        for (int i = 0; i < 3; i++)
            for (int j = 0; j < 3; j++) t2[i + j] = fmaf(t1[i], t1[j], t2[i + j]);
        for (int k = 0; k < 7; k++) t3[k] = 0.f;
        for (int i = 0; i < 3; i++)
            for (int j = 0; j < 5; j++) t3[i + j] = fmaf(t1[i], t2[j], t3[i + j]);
        for (int k = 0; k < 9; k++) t4[k] = 0.f;
        for (int i = 0; i < 5; i++)
            for (int j = 0; j < 5; j++) t4[i + j] = fmaf(t2[i], t2[j], t4[i + j]);

        // doubling level: minimal L (<=2) with 2^L * Di >= NTH
        int L = 0, lb = Di;
        while (L < 2 && lb < NTH) { L++; lb <<= 1; }
        s_lagbase = lb;
        s_Cb      = min(NTH, lb);

        if (L == 0) {
            s_nser = 3; for (int k = 0; k < 3; k++) s_ser[k] = t1[k];
            s_npre = 0;
        } else if (L == 1) {
            s_nser = 5; for (int k = 0; k < 5; k++) s_ser[k] = t2[k];
            s_npre = 3;
            for (int k = 0; k < 3; k++) { s_pc[k] = t1[k]; s_po[k] = Di + k; }
        } else {
            s_nser = 9; for (int k = 0; k < 9; k++) s_ser[k] = t4[k];
            s_npre = 15;
            int q = 0;
            for (int k = 0; k < 3; k++, q++) { s_pc[q] = t1[k]; s_po[q] = Di + k; }
            for (int k = 0; k < 5; k++, q++) { s_pc[q] = t2[k]; s_po[q] = 2 * Di + k; }
            for (int k = 0; k < 7; k++, q++) { s_pc[q] = t3[k]; s_po[q] = 3 * Di + k; }
        }
    }

    if (b == 0) {
        if (tid >= 32 && tid < 32 + BATCH) {
            int bb = tid - 32;
            mlp_eval(pitch[bb], w1, b1, w2, b2, s_lc[bb], s_lm[bb], s_lp[bb]);
        }
        if (tid >= 64 && tid < 64 + NB) {
            int band = tid - 64;
            double fc  = 80.0 * exp(log(100.0) * (double)band / 23.0);
            float  fcf = (float)fc;
            float  w   = 2.f * PI_F * fcf / FS_F;
            float  r   = expf(-PI_F * fcf / (10.f * FS_F));
            float  a1  = -2.f * r * cosf(w);
            float  a2  = r * r;
            d_bA1[band] = a1; d_bA2[band] = a2; d_bB0[band] = 1.f - r;
            // scan-level powers M^(128*2^j), all in double (non-normal matrix
            // powers cancel catastrophically in float).
            double ma = -(double)a1, mb = -(double)a2, mc = 1.0, md = 0.0;
            for (int it = 0; it < 7; it++) {
                double na = ma * ma + mb * mc;
                double nb = ma * mb + mb * md;
                double nc = mc * ma + md * mc;
                double nd = mc * mb + md * md;
                ma = na; mb = nb; mc = nc; md = nd;
            }
            for (int j = 0; j < NLVL; j++) {
                d_Pl[band][j][0] = (float)ma; d_Pl[band][j][1] = (float)mb;
                d_Pl[band][j][2] = (float)mc; d_Pl[band][j][3] = (float)md;
                double na = ma * ma + mb * mc;
                double nb = ma * mb + mb * md;
                double nc = mc * ma + md * mc;
                double nd = mc * mb + md * md;
                ma = na; mb = nb; mc = nc; md = nd;
            }
        }
    }
    __syncthreads();

    if (b == 0 && tid == 0 && write_scalars) {
        float sc = 0.f, smm = 0.f, spp = 0.f;
        for (int i = 0; i < BATCH; i++) { sc += s_lc[i]; smm += s_lm[i]; spp += s_lp[i]; }
        out_tail[0] = sc  / (float)BATCH;
        out_tail[1] = smm / (float)BATCH;
        out_tail[2] = spp / (float)BATCH;
    }

    // load excitation + zero KS ring
    const float* xin = exc + b * NSMP;
    for (int i = tid; i < NSMP; i += NTH) sig[i] = xin[i];
    for (int i = tid; i < KSL; i += NTH) buf[i] = 0.f;
    __syncthreads();

    // pre one-pole LP
    lp_inplace(sig, scan, s_mpre, s_scpre, tid);

    // KS: pre-multiply then doubled serial recurrence
    if (s_npre == 3)       ks_prepass<3>(sig, s_pc, s_po, tid);
    else if (s_npre == 15) ks_prepass<15>(sig, s_pc, s_po, tid);

    if (s_nser == 3)       ks_serial<3>(sig, buf, s_ser, s_lagbase, s_Cb, tid);
    else if (s_nser == 5)  ks_serial<5>(sig, buf, s_ser, s_lagbase, s_Cb, tid);
    else                   ks_serial<9>(sig, buf, s_ser, s_lagbase, s_Cb, tid);

    // post one-pole LP
    lp_inplace(sig, scan, s_mpost, s_scpost, tid);

    // write string out for the body stage
    float* yout = d_scr + b * NSMP;
    for (int i = tid; i < NSMP; i += NTH) yout[i] = sig[i];
}

// ---------------------------------------------------------------------------
// bodyAB: block = (band, batch), 256 threads. Thread c runs chunk c's
// zero-init 2-pole (signal staged in skewed smem, stride 129 -> conflict-
// free lane access), then in-block affine scan of the 256 chunk states with
// the exact double-computed level matrices. Writes exclusive init states.
// ---------------------------------------------------------------------------
__global__ void bodyAB_kernel()
{
    extern __shared__ float sh[];           // [BC*129] skewed signal
    __shared__ float2 st[BC];
    int band = blockIdx.x, b = blockIdx.y, c = threadIdx.x;

    const float* x = d_scr + b * NSMP;
    for (int i = c; i < NSMP; i += BC) {
        int cc = i >> 7, t = i & 127;
        sh[cc * 129 + t] = x[i];
    }
    __syncthreads();

    float a1 = d_bA1[band], a2 = d_bA2[band], b0 = d_bB0[band];
    const float* xs = sh + c * 129;
    float y1 = 0.f, y2 = 0.f;
    #pragma unroll 8
    for (int t = 0; t < BL; t++) {
        float u = fmaf(-a2, y2, b0 * xs[t]);
        float y = fmaf(-a1, y1, u);
        y2 = y1; y1 = y;
    }

    float2 v = make_float2(y1, y2);
    st[c] = v;
    __syncthreads();
    #pragma unroll
    for (int j = 0; j < NLVL; j++) {
        int ofs = 1 << j;
        float q00 = d_Pl[band][j][0], q01 = d_Pl[band][j][1];
        float q10 = d_Pl[band][j][2], q11 = d_Pl[band][j][3];
        float2 pv = (c >= ofs) ? st[c - ofs] : make_float2(0.f, 0.f);
        __syncthreads();
        v.x = fmaf(q00, pv.x, fmaf(q01, pv.y, v.x));
        v.y = fmaf(q10, pv.x, fmaf(q11, pv.y, v.y));
        st[c] = v;
        __syncthreads();
    }
    d_initS[b][c][band] = (c > 0) ? st[c - 1] : make_float2(0.f, 0.f);
}

// ---------------------------------------------------------------------------
// bodyC: recompute chunks with correct init, weighted band sum.
// ---------------------------------------------------------------------------
__global__ void bodyC_kernel(const float* __restrict__ gains, float* __restrict__ out)
{
    __shared__ float shx[BL];
    __shared__ float tile[BL * 25];   // [t][band], stride 25 (pad)
    __shared__ float shg[NB];
    int b = blockIdx.y, c = blockIdx.x, tid = threadIdx.x;
    const float* x = d_scr + b * NSMP + c * BL;
    for (int i = tid; i < BL; i += 32) shx[i] = x[i];
    if (tid < NB) shg[tid] = gains[tid];
    __syncthreads();

    if (tid < NB) {
        float a1 = d_bA1[tid], a2 = d_bA2[tid], b0 = d_bB0[tid];
        float2 s = d_initS[b][c][tid];
        float y1 = s.x, y2 = s.y;
        #pragma unroll 8
        for (int t = 0; t < BL; t++) {
            float u = fmaf(-a2, y2, b0 * shx[t]);
            float y = fmaf(-a1, y1, u);
            tile[t * 25 + tid] = y;
            y2 = y1; y1 = y;
        }
    }
    __syncthreads();

    for (int t = tid; t < BL; t += 32) {
        float acc = 0.f;
        #pragma unroll
        for (int k = 0; k < NB; k++) acc = fmaf(tile[t * 25 + k], shg[k], acc);
        out[b * NSMP + c * BL + t] = acc;
    }
}

// ---------------------------------------------------------------------------
extern "C" void kernel_launch(void* const* d_in, const int* in_sizes, int n_in,
                              void* d_out, int out_size)
{
    const float* exc   = (const float*)d_in[0];   // [8,1,32768]
    const float* pitch = (const float*)d_in[1];   // [8,1]
    const float* w1    = (const float*)d_in[2];   // [16,1]
    const float* b1    = (const float*)d_in[3];   // [16]
    const float* w2    = (const float*)d_in[4];   // [3,16]
    const float* b2    = (const float*)d_in[5];   // [3]
    const float* eg    = (const float*)d_in[6];   // scalar
    const float* bg    = (const float*)d_in[7];   // [1,24]
    float* out = (float*)d_out;

    int wr = (out_size >= BATCH * NSMP + 3) ? 1 : 0;

    const int smem_fused = (NSMP + KSL + NTH) * (int)sizeof(float);   // ~136 KB
    const int smem_body  = (BC * 129) * (int)sizeof(float);           // ~129 KB
    cudaFuncSetAttribute(fused_kernel,
                         cudaFuncAttributeMaxDynamicSharedMemorySize, smem_fused);
    cudaFuncSetAttribute(bodyAB_kernel,
                         cudaFuncAttributeMaxDynamicSharedMemorySize, smem_body);

    fused_kernel<<<BATCH, NTH, smem_fused>>>(exc, pitch, w1, b1, w2, b2, eg,
                                             out + BATCH * NSMP, wr);
    bodyAB_kernel<<<dim3(NB, BATCH), BC, smem_body>>>();
    bodyC_kernel<<<dim3(BC, BATCH), 32>>>(bg, out);
}

// round 5
// speedup vs baseline: 1.1087x; 1.1087x over previous
#include <cuda_runtime.h>
#include <math.h>

// ---------------------------------------------------------------------------
// AcousticGuitarPoC: fused (params + pre-LP + doubled KS with inline input
// FIR + post-LP) -> bodyA/bodyB/bodyC parallel resonator bank.
// B=8, N=32768. 4 kernel launches.
// ---------------------------------------------------------------------------

#define FS_F   44100.0f
#define PI_F   3.14159265358979323846f
#define NB     24
#define NSMP   32768
#define BATCH  8
#define NTH    256      // fused-kernel threads; KS chunk size
#define LCH    128      // LP chunk length (256*128 = 32768)
#define KSL    1024     // KS ring (power of 2; max age lag+8 <= 743 < 1024)
#define KDEL   3        // y->sig writeback delay in chunks
#define BL     128      // body chunk length
#define BC     256      // body chunk count (256*128 = 32768)
#define NLVL   8        // log2(BC) scan levels

__device__ float  d_bA1[NB], d_bA2[NB], d_bB0[NB];
__device__ float  d_Pl[NB][NLVL][4];          // M^(BL*2^j), double-computed
__device__ float  d_scr[BATCH * NSMP];        // string output for body stage
__device__ float2 d_carry[BATCH][BC][NB];     // body zero-init chunk end states
__device__ float2 d_initS[BATCH][BC][NB];     // body corrected chunk init states

__device__ __forceinline__ float sigm(float x) { return 1.f / (1.f + expf(-x)); }
__device__ __forceinline__ float clampf(float x, float lo, float hi) {
    return fminf(fmaxf(x, lo), hi);
}

__device__ __forceinline__ void mlp_eval(float p,
    const float* __restrict__ w1, const float* __restrict__ b1,
    const float* __restrict__ w2, const float* __restrict__ b2,
    float& lc, float& lm, float& lp)
{
    float m0 = b2[0], m1 = b2[1], m2 = b2[2];
    #pragma unroll
    for (int j = 0; j < 16; j++) {
        float h = fmaxf(fmaf(p, w1[j], b1[j]), 0.f);
        m0 = fmaf(h, w2[j],      m0);
        m1 = fmaf(h, w2[16 + j], m1);
        m2 = fmaf(h, w2[32 + j], m2);
    }
    lc = clampf(m0, -2.0f, 2.5f);
    lm = clampf(m1, -2.5f, 0.0f);
    lp = clampf(m2, -4.0f, 4.0f);
}

// In-place one-pole LP: y[n] = m*y[n-1] + sc*x[n]; chunked + carry scan.
__device__ void lp_inplace(float* sig, float* scanbuf, float m, float sc, int tid)
{
    float* x = sig + tid * LCH;

    float e = 0.f;
    #pragma unroll 8
    for (int k = 0; k < LCH; k++) e = fmaf(m, e, sc * x[k]);

    scanbuf[tid] = e;
    __syncthreads();

    float f = m;
    #pragma unroll
    for (int i = 0; i < 7; i++) f *= f;       // m^128

    #pragma unroll
    for (int ofs = 1; ofs < NTH; ofs <<= 1) {
        float v = (tid >= ofs) ? scanbuf[tid - ofs] : 0.f;
        __syncthreads();
        e = fmaf(f, v, e);
        scanbuf[tid] = e;
        f *= f;
        __syncthreads();
    }

    float yp = (tid > 0) ? scanbuf[tid - 1] : 0.f;
    #pragma unroll 8
    for (int k = 0; k < LCH; k++) { yp = fmaf(m, yp, sc * x[k]); x[k] = yp; }
    __syncthreads();
}

// Doubled KS serial loop with inline input FIR. sig stays pristine x during
// the loop (y goes to the ring; y->sig writes are delayed KDEL chunks, a
// region strictly below any FIR read). One __syncthreads per 256-chunk;
// always 128 chunks.  y[n] = xfir[n] + sum_j sc[j] * y[n - lag - j],
// xfir[n] = sig[n] + sum_t xc[t] * sig[n - xo[t]].
template<int NSER, int NX>
__device__ __forceinline__ void ks_fused(float* sig, float* buf,
    const float* __restrict__ serc, const float* __restrict__ xco,
    const int* __restrict__ xoo, int lag, int tid)
{
    float sc[NSER];
    #pragma unroll
    for (int j = 0; j < NSER; j++) sc[j] = serc[j];
    float xc[NX > 0 ? NX : 1]; int xo[NX > 0 ? NX : 1];
    #pragma unroll
    for (int t = 0; t < NX; t++) { xc[t] = xco[t]; xo[t] = xoo[t]; }

    float ydel0 = 0.f, ydel1 = 0.f, ydel2 = 0.f;

    for (int k = 0; k < NSMP / NTH; k++) {
        int n = k * NTH + tid;

        // input FIR from pristine x (no cross-chunk hazard)
        float acc = sig[n];
        #pragma unroll
        for (int t = 0; t < NX; t++) {
            int idx = n - xo[t];
            float v = (idx >= 0) ? sig[idx] : 0.f;
            acc = fmaf(xc[t], v, acc);
        }

        // ring feedback (negative-time slots still hold their initial zeros:
        // slot idx+1024 is first written at sample idx+1024 > n since
        // lag+j <= 743 < 1024)
        int p = n - lag;
        float fb = 0.f;
        #pragma unroll
        for (int j = 0; j < NSER; j++)
            fb = fmaf(sc[j], buf[(p - j) & (KSL - 1)], fb);
        float y = acc + fb;

        buf[n & (KSL - 1)] = y;

        // delayed writeback of y into sig (region [n-768, ...), below all
        // FIR reads which reach back < 390)
        if (k >= KDEL) sig[n - KDEL * NTH] = ydel0;
        ydel0 = ydel1; ydel1 = ydel2; ydel2 = y;

        __syncthreads();
    }
    // flush last KDEL chunks
    sig[NSMP - 3 * NTH + tid] = ydel0;
    sig[NSMP - 2 * NTH + tid] = ydel1;
    sig[NSMP - 1 * NTH + tid] = ydel2;
    __syncthreads();
}

// ---------------------------------------------------------------------------
// Fused kernel: one block per batch.
// ---------------------------------------------------------------------------
__global__ void fused_kernel(const float* __restrict__ exc,
                             const float* __restrict__ pitch,
                             const float* __restrict__ w1,
                             const float* __restrict__ b1,
                             const float* __restrict__ w2,
                             const float* __restrict__ b2,
                             const float* __restrict__ egain,
                             float* out_tail, int write_scalars)
{
    extern __shared__ float sm[];
    float* sig  = sm;              // [NSMP]
    float* buf  = sm + NSMP;       // [KSL]
    float* scan = buf + KSL;       // [NTH]

    __shared__ float s_mpre, s_scpre, s_mpost, s_scpost;
    __shared__ float s_ser[9], s_pc[15];
    __shared__ int   s_po[15], s_L, s_lag;
    __shared__ float s_lc[BATCH], s_lm[BATCH], s_lp[BATCH];

    int b = blockIdx.x, tid = threadIdx.x;

    if (tid == 0) {
        float p = pitch[b];
        float lc, lm, lp;
        mlp_eval(p, w1, b1, w2, b2, lc, lm, lp);

        float g = 0.999f * sigm(lc);
        float s = sigm(lm);
        float gs  = g * s;
        float g1s = g * (1.f - s);

        float f0    = fmaxf(p, 60.f);
        float mult  = clampf(2.f + 6.f * (f0 - 60.f) / 600.f, 2.f, 8.f);
        float cut   = fminf(2.f * PI_F * f0 * mult / FS_F, PI_F * 0.9f);
        float alpha = 1.f - expf(-cut);
        s_mpre  = 1.f - alpha;
        s_scpre = alpha * egain[0];

        float cutp = fminf(PI_F * sigm(lp), PI_F * 0.99f);
        float ap   = 1.f - expf(-cutp);
        s_mpost  = 1.f - ap;
        s_scpost = ap;

        float D  = clampf(FS_F / f0, 2.f, 735.f);
        float Df = floorf(D);
        int   Di = (int)Df;
        float fr = D - Df;

        // base 3-tap loop: y[n] = x[n] + c1 y[n-Di] + c2 y[n-Di-1] + c3 y[n-Di-2]
        float t1[3], t2[5], t3[7], t4[9];
        t1[0] = g1s * (1.f - fr);
        t1[1] = g1s * fr + gs * (1.f - fr);
        t1[2] = gs * fr;
        for (int k = 0; k < 5; k++) t2[k] = 0.f;
        for (int i = 0; i < 3; i++)
            for (int j = 0; j < 3; j++) t2[i + j] = fmaf(t1[i], t1[j], t2[i + j]);
        for (int k = 0; k < 7; k++) t3[k] = 0.f;
        for (int i = 0; i < 3; i++)
            for (int j = 0; j < 5; j++) t3[i + j] = fmaf(t1[i], t2[j], t3[i + j]);
        for (int k = 0; k < 9; k++) t4[k] = 0.f;
        for (int i = 0; i < 5; i++)
            for (int j = 0; j < 5; j++) t4[i + j] = fmaf(t2[i], t2[j], t4[i + j]);

        // doubling level: minimal L (<=2) with 2^L * Di >= NTH
        int L = 0, lb = Di;
        while (L < 2 && lb < NTH) { L++; lb <<= 1; }
        s_L = L; s_lag = lb;

        if (L == 0) {
            for (int k = 0; k < 3; k++) s_ser[k] = t1[k];
        } else if (L == 1) {
            for (int k = 0; k < 5; k++) s_ser[k] = t2[k];
            for (int k = 0; k < 3; k++) { s_pc[k] = t1[k]; s_po[k] = Di + k; }
        } else {
            for (int k = 0; k < 9; k++) s_ser[k] = t4[k];
            int q = 0;
            for (int k = 0; k < 3; k++, q++) { s_pc[q] = t1[k]; s_po[q] = Di + k; }
            for (int k = 0; k < 5; k++, q++) { s_pc[q] = t2[k]; s_po[q] = 2 * Di + k; }
            for (int k = 0; k < 7; k++, q++) { s_pc[q] = t3[k]; s_po[q] = 3 * Di + k; }
        }
    }

    if (b == 0) {
        if (tid >= 32 && tid < 32 + BATCH) {
            int bb = tid - 32;
            mlp_eval(pitch[bb], w1, b1, w2, b2, s_lc[bb], s_lm[bb], s_lp[bb]);
        }
        if (tid >= 64 && tid < 64 + NB) {
            int band = tid - 64;
            double fc  = 80.0 * exp(log(100.0) * (double)band / 23.0);
            float  fcf = (float)fc;
            float  w   = 2.f * PI_F * fcf / FS_F;
            float  r   = expf(-PI_F * fcf / (10.f * FS_F));
            float  a1  = -2.f * r * cosf(w);
            float  a2  = r * r;
            d_bA1[band] = a1; d_bA2[band] = a2; d_bB0[band] = 1.f - r;
            // scan-level powers M^(128*2^j), all in double (non-normal matrix
            // powers cancel catastrophically in float).
            double ma = -(double)a1, mb = -(double)a2, mc = 1.0, md = 0.0;
            for (int it = 0; it < 7; it++) {
                double na = ma * ma + mb * mc;
                double nb = ma * mb + mb * md;
                double nc = mc * ma + md * mc;
                double nd = mc * mb + md * md;
                ma = na; mb = nb; mc = nc; md = nd;
            }
            for (int j = 0; j < NLVL; j++) {
                d_Pl[band][j][0] = (float)ma; d_Pl[band][j][1] = (float)mb;
                d_Pl[band][j][2] = (float)mc; d_Pl[band][j][3] = (float)md;
                double na = ma * ma + mb * mc;
                double nb = ma * mb + mb * md;
                double nc = mc * ma + md * mc;
                double nd = mc * mb + md * md;
                ma = na; mb = nb; mc = nc; md = nd;
            }
        }
    }
    __syncthreads();

    if (b == 0 && tid == 0 && write_scalars) {
        float sc = 0.f, smm = 0.f, spp = 0.f;
        for (int i = 0; i < BATCH; i++) { sc += s_lc[i]; smm += s_lm[i]; spp += s_lp[i]; }
        out_tail[0] = sc  / (float)BATCH;
        out_tail[1] = smm / (float)BATCH;
        out_tail[2] = spp / (float)BATCH;
    }

    // load excitation + zero KS ring
    const float* xin = exc + b * NSMP;
    for (int i = tid; i < NSMP; i += NTH) sig[i] = xin[i];
    for (int i = tid; i < KSL; i += NTH) buf[i] = 0.f;
    __syncthreads();

    // pre one-pole LP
    lp_inplace(sig, scan, s_mpre, s_scpre, tid);

    // Karplus-Strong, doubled with inline input FIR
    int L = s_L, lag = s_lag;
    if (L == 0)      ks_fused<3, 0>(sig, buf, s_ser, s_pc, s_po, lag, tid);
    else if (L == 1) ks_fused<5, 3>(sig, buf, s_ser, s_pc, s_po, lag, tid);
    else             ks_fused<9, 15>(sig, buf, s_ser, s_pc, s_po, lag, tid);

    // post one-pole LP
    lp_inplace(sig, scan, s_mpost, s_scpost, tid);

    // write string out for the body stage
    float* yout = d_scr + b * NSMP;
    for (int i = tid; i < NSMP; i += NTH) yout[i] = sig[i];
}

// ---------------------------------------------------------------------------
// Body pass A: per (chunk, batch) 1-warp block, lane = band.
// ---------------------------------------------------------------------------
__global__ void bodyA_kernel()
{
    __shared__ float shx[BL];
    int b = blockIdx.y, c = blockIdx.x, tid = threadIdx.x;
    const float* x = d_scr + b * NSMP + c * BL;
    for (int i = tid; i < BL; i += 32) shx[i] = x[i];
    __syncthreads();
    if (tid < NB) {
        float a1 = d_bA1[tid], a2 = d_bA2[tid], b0 = d_bB0[tid];
        float y1 = 0.f, y2 = 0.f;
        #pragma unroll 8
        for (int t = 0; t < BL; t++) {
            float u = fmaf(-a2, y2, b0 * shx[t]);
            float y = fmaf(-a1, y1, u);
            y2 = y1; y1 = y;
        }
        d_carry[b][c][tid] = make_float2(y1, y2);
    }
}

// ---------------------------------------------------------------------------
// Body pass B: parallel affine scan of chunk carries with exact
// (double-computed) level matrices. Exclusive -> d_initS.
// ---------------------------------------------------------------------------
__global__ void bodyB_kernel()
{
    __shared__ float2 s[BC];
    int band = blockIdx.x, b = blockIdx.y, c = threadIdx.x;
    float2 v = d_carry[b][c][band];
    s[c] = v;
    __syncthreads();
    #pragma unroll
    for (int j = 0; j < NLVL; j++) {
        int ofs = 1 << j;
        float q00 = d_Pl[band][j][0], q01 = d_Pl[band][j][1];
        float q10 = d_Pl[band][j][2], q11 = d_Pl[band][j][3];
        float2 pv = (c >= ofs) ? s[c - ofs] : make_float2(0.f, 0.f);
        __syncthreads();
        v.x = fmaf(q00, pv.x, fmaf(q01, pv.y, v.x));
        v.y = fmaf(q10, pv.x, fmaf(q11, pv.y, v.y));
        s[c] = v;
        __syncthreads();
    }
    d_initS[b][c][band] = (c > 0) ? s[c - 1] : make_float2(0.f, 0.f);
}

// ---------------------------------------------------------------------------
// Body pass C: recompute chunks with correct init, weighted band sum.
// ---------------------------------------------------------------------------
__global__ void bodyC_kernel(const float* __restrict__ gains, float* __restrict__ out)
{
    __shared__ float shx[BL];
    __shared__ float tile[BL * 25];   // [t][band], stride 25 (pad)
    __shared__ float shg[NB];
    int b = blockIdx.y, c = blockIdx.x, tid = threadIdx.x;
    const float* x = d_scr + b * NSMP + c * BL;
    for (int i = tid; i < BL; i += 32) shx[i] = x[i];
    if (tid < NB) shg[tid] = gains[tid];
    __syncthreads();

    if (tid < NB) {
        float a1 = d_bA1[tid], a2 = d_bA2[tid], b0 = d_bB0[tid];
        float2 s = d_initS[b][c][tid];
        float y1 = s.x, y2 = s.y;
        #pragma unroll 8
        for (int t = 0; t < BL; t++) {
            float u = fmaf(-a2, y2, b0 * shx[t]);
            float y = fmaf(-a1, y1, u);
            tile[t * 25 + tid] = y;
            y2 = y1; y1 = y;
        }
    }
    __syncthreads();

    for (int t = tid; t < BL; t += 32) {
        float acc = 0.f;
        #pragma unroll
        for (int k = 0; k < NB; k++) acc = fmaf(tile[t * 25 + k], shg[k], acc);
        out[b * NSMP + c * BL + t] = acc;
    }
}

// ---------------------------------------------------------------------------
extern "C" void kernel_launch(void* const* d_in, const int* in_sizes, int n_in,
                              void* d_out, int out_size)
{
    const float* exc   = (const float*)d_in[0];   // [8,1,32768]
    const float* pitch = (const float*)d_in[1];   // [8,1]
    const float* w1    = (const float*)d_in[2];   // [16,1]
    const float* b1    = (const float*)d_in[3];   // [16]
    const float* w2    = (const float*)d_in[4];   // [3,16]
    const float* b2    = (const float*)d_in[5];   // [3]
    const float* eg    = (const float*)d_in[6];   // scalar
    const float* bg    = (const float*)d_in[7];   // [1,24]
    float* out = (float*)d_out;

    int wr = (out_size >= BATCH * NSMP + 3) ? 1 : 0;

    const int smem_fused = (NSMP + KSL + NTH) * (int)sizeof(float);   // ~136 KB
    cudaFuncSetAttribute(fused_kernel,
                         cudaFuncAttributeMaxDynamicSharedMemorySize, smem_fused);

    fused_kernel<<<BATCH, NTH, smem_fused>>>(exc, pitch, w1, b1, w2, b2, eg,
                                             out + BATCH * NSMP, wr);
    bodyA_kernel<<<dim3(BC, BATCH), 32>>>();
    bodyB_kernel<<<dim3(NB, BATCH), BC>>>();
    bodyC_kernel<<<dim3(BC, BATCH), 32>>>(bg, out);
}

// round 6
// speedup vs baseline: 1.5106x; 1.3626x over previous
#include <cuda_runtime.h>
#include <math.h>

// ---------------------------------------------------------------------------
// AcousticGuitarPoC: fused (params + pre-LP + adaptive-doubled KS + post-LP)
// -> bodyA/bodyB/bodyC parallel resonator bank. B=8, N=32768. 4 launches.
// ---------------------------------------------------------------------------

#define FS_F   44100.0f
#define PI_F   3.14159265358979323846f
#define NB     24
#define NSMP   32768
#define BATCH  8
#define NTH    256      // fused-kernel threads
#define LCH    128      // LP chunk length (256*128 = 32768)
#define KSL    1024     // KS ring (power of 2)
#define BL     128      // body chunk length
#define BC     256      // body chunk count (256*128 = 32768)
#define NLVL   8        // log2(BC) scan levels

__device__ float  d_bA1[NB], d_bA2[NB], d_bB0[NB];
__device__ float  d_Pl[NB][NLVL][4];          // M^(BL*2^j), double-computed
__device__ float  d_scr[BATCH * NSMP];        // string output for body stage
__device__ float2 d_carry[BATCH][BC][NB];     // body zero-init chunk end states
__device__ float2 d_initS[BATCH][BC][NB];     // body corrected chunk init states

__device__ __forceinline__ float sigm(float x) { return 1.f / (1.f + expf(-x)); }
__device__ __forceinline__ float clampf(float x, float lo, float hi) {
    return fminf(fmaxf(x, lo), hi);
}

__device__ __forceinline__ void mlp_eval(float p,
    const float* __restrict__ w1, const float* __restrict__ b1,
    const float* __restrict__ w2, const float* __restrict__ b2,
    float& lc, float& lm, float& lp)
{
    float m0 = b2[0], m1 = b2[1], m2 = b2[2];
    #pragma unroll
    for (int j = 0; j < 16; j++) {
        float h = fmaxf(fmaf(p, w1[j], b1[j]), 0.f);
        m0 = fmaf(h, w2[j],      m0);
        m1 = fmaf(h, w2[16 + j], m1);
        m2 = fmaf(h, w2[32 + j], m2);
    }
    lc = clampf(m0, -2.0f, 2.5f);
    lm = clampf(m1, -2.5f, 0.0f);
    lp = clampf(m2, -4.0f, 4.0f);
}

// In-place one-pole LP: y[n] = m*y[n-1] + sc*x[n].
// Chunked serial + shuffle-based carry scan (only 2 block barriers).
__device__ void lp_inplace(float* sig, float* ws, float m, float sc, int tid)
{
    int lane = tid & 31, wid = tid >> 5;
    float* x = sig + tid * LCH;

    float e = 0.f;
    #pragma unroll 8
    for (int k = 0; k < LCH; k++) e = fmaf(m, e, sc * x[k]);

    float f128 = m;
    #pragma unroll
    for (int i = 0; i < 7; i++) f128 *= f128;   // m^128

    // warp-inclusive affine scan: y[c] = f128*y[c-1] + e[c]
    float f = f128;
    #pragma unroll
    for (int ofs = 1; ofs < 32; ofs <<= 1) {
        float v = __shfl_up_sync(0xffffffffu, e, ofs);
        if (lane >= ofs) e = fmaf(f, v, e);
        f *= f;
    }
    // f is now m^4096 = step factor between warp totals

    if (lane == 31) ws[wid] = e;
    __syncthreads();
    if (wid == 0 && lane < 8) {
        float t = ws[lane];
        float g = f;
        #pragma unroll
        for (int ofs = 1; ofs < 8; ofs <<= 1) {
            float v = __shfl_up_sync(0x000000ffu, t, ofs);
            if (lane >= ofs) t = fmaf(g, v, t);
            g *= g;
        }
        ws[lane] = t;
    }
    __syncthreads();

    float carry = (wid > 0) ? ws[wid - 1] : 0.f;
    // lane multiplier m^(128*(lane+1)); f128 in (0,1) so log2f is safe
    float lmul = exp2f((float)(lane + 1) * log2f(f128));
    float Y = fmaf(lmul, carry, e);          // block-inclusive scan value
    float yp = __shfl_up_sync(0xffffffffu, Y, 1);
    if (lane == 0) yp = carry;
    if (tid == 0)  yp = 0.f;

    #pragma unroll 8
    for (int k = 0; k < LCH; k++) { yp = fmaf(m, yp, sc * x[k]); x[k] = yp; }
    __syncthreads();
}

// ---------------------------------------------------------------------------
// Fused kernel: one block per batch.
// ---------------------------------------------------------------------------
__global__ void fused_kernel(const float* __restrict__ exc,
                             const float* __restrict__ pitch,
                             const float* __restrict__ w1,
                             const float* __restrict__ b1,
                             const float* __restrict__ w2,
                             const float* __restrict__ b2,
                             const float* __restrict__ egain,
                             float* out_tail, int write_scalars)
{
    extern __shared__ float sm[];
    float* sig  = sm;              // [NSMP]
    float* buf  = sm + NSMP;       // [KSL]
    float* scan = buf + KSL;       // [NTH]

    __shared__ float s_mpre, s_scpre, s_mpost, s_scpost;
    __shared__ float s_ser[5], s_fc[3];
    __shared__ int   s_L, s_Di, s_lag, s_Cb, s_nwT;
    __shared__ float s_lc[BATCH], s_lm[BATCH], s_lp[BATCH];

    int b = blockIdx.x, tid = threadIdx.x;

    if (tid == 0) {
        float p = pitch[b];
        float lc, lm, lp;
        mlp_eval(p, w1, b1, w2, b2, lc, lm, lp);

        float g = 0.999f * sigm(lc);
        float s = sigm(lm);
        float gs  = g * s;
        float g1s = g * (1.f - s);

        float f0    = fmaxf(p, 60.f);
        float mult  = clampf(2.f + 6.f * (f0 - 60.f) / 600.f, 2.f, 8.f);
        float cut   = fminf(2.f * PI_F * f0 * mult / FS_F, PI_F * 0.9f);
        float alpha = 1.f - expf(-cut);
        s_mpre  = 1.f - alpha;
        s_scpre = alpha * egain[0];

        float cutp = fminf(PI_F * sigm(lp), PI_F * 0.99f);
        float ap   = 1.f - expf(-cutp);
        s_mpost  = 1.f - ap;
        s_scpost = ap;

        float D  = clampf(FS_F / f0, 2.f, 735.f);
        float Df = floorf(D);
        int   Di = (int)Df;
        float fr = D - Df;
        s_Di = Di;

        // base loop: y[n] = x[n] + t1[0] y[n-Di] + t1[1] y[n-Di-1] + t1[2] y[n-Di-2]
        float t1[3];
        t1[0] = g1s * (1.f - fr);
        t1[1] = g1s * fr + gs * (1.f - fr);
        t1[2] = gs * fr;

        if (Di - 2 >= 254) {
            // L = 0: plain recurrence, rounds <= 129
            s_L   = 0;
            s_lag = Di;
            s_Cb  = min(256, Di - 2);
            for (int k = 0; k < 3; k++) s_ser[k] = t1[k];
            s_ser[3] = 0.f; s_ser[4] = 0.f;
            s_fc[0] = s_fc[1] = s_fc[2] = 0.f;
        } else {
            // L = 1: (1 - C^2) y = (1 + C) x
            float t2[5];
            for (int k = 0; k < 5; k++) t2[k] = 0.f;
            for (int i = 0; i < 3; i++)
                for (int j = 0; j < 3; j++) t2[i + j] = fmaf(t1[i], t1[j], t2[i + j]);
            s_L   = 1;
            s_lag = 2 * Di;
            s_Cb  = min(256, 2 * Di);
            for (int k = 0; k < 5; k++) s_ser[k] = t2[k];
            for (int k = 0; k < 3; k++) s_fc[k]  = t1[k];
        }
        s_nwT = ((s_Cb + 31) >> 5) << 5;
    }

    if (b == 0) {
        if (tid >= 32 && tid < 32 + BATCH) {
            int bb = tid - 32;
            mlp_eval(pitch[bb], w1, b1, w2, b2, s_lc[bb], s_lm[bb], s_lp[bb]);
        }
        if (tid >= 64 && tid < 64 + NB) {
            int band = tid - 64;
            double fc  = 80.0 * exp(log(100.0) * (double)band / 23.0);
            float  fcf = (float)fc;
            float  w   = 2.f * PI_F * fcf / FS_F;
            float  r   = expf(-PI_F * fcf / (10.f * FS_F));
            float  a1  = -2.f * r * cosf(w);
            float  a2  = r * r;
            d_bA1[band] = a1; d_bA2[band] = a2; d_bB0[band] = 1.f - r;
            // scan-level powers M^(128*2^j), all in double (non-normal matrix
            // powers cancel catastrophically in float).
            double ma = -(double)a1, mb = -(double)a2, mc = 1.0, md = 0.0;
            for (int it = 0; it < 7; it++) {
                double na = ma * ma + mb * mc;
                double nb = ma * mb + mb * md;
                double nc = mc * ma + md * mc;
                double nd = mc * mb + md * md;
                ma = na; mb = nb; mc = nc; md = nd;
            }
            for (int j = 0; j < NLVL; j++) {
                d_Pl[band][j][0] = (float)ma; d_Pl[band][j][1] = (float)mb;
                d_Pl[band][j][2] = (float)mc; d_Pl[band][j][3] = (float)md;
                double na = ma * ma + mb * mc;
                double nb = ma * mb + mb * md;
                double nc = mc * ma + md * mc;
                double nd = mc * mb + md * md;
                ma = na; mb = nb; mc = nc; md = nd;
            }
        }
    }
    __syncthreads();

    if (b == 0 && tid == 0 && write_scalars) {
        float sc = 0.f, smm = 0.f, spp = 0.f;
        for (int i = 0; i < BATCH; i++) { sc += s_lc[i]; smm += s_lm[i]; spp += s_lp[i]; }
        out_tail[0] = sc  / (float)BATCH;
        out_tail[1] = smm / (float)BATCH;
        out_tail[2] = spp / (float)BATCH;
    }

    // load excitation + zero KS ring
    const float* xin = exc + b * NSMP;
    for (int i = tid; i < NSMP; i += NTH) sig[i] = xin[i];
    for (int i = tid; i < KSL; i += NTH) buf[i] = 0.f;
    __syncthreads();

    // pre one-pole LP
    lp_inplace(sig, scan, s_mpre, s_scpre, tid);

    // ---------------- Karplus-Strong ----------------
    {
        int Di = s_Di, lag = s_lag, Cb = s_Cb, nwT = s_nwT, L = s_L;
        float c0 = s_ser[0], c1 = s_ser[1], c2 = s_ser[2],
              c3 = s_ser[3], c4 = s_ser[4];
        float f0c = s_fc[0], f1c = s_fc[1], f2c = s_fc[2];

        if (L == 0) {
            // plain 3-tap recurrence; named barrier over participating warps
            if (tid < nwT) {
                for (int base = 0; base < NSMP; base += Cb) {
                    int n = base + tid;
                    if (tid < Cb && n < NSMP) {
                        float acc = sig[n];
                        acc = fmaf(c0, buf[(n - Di     + 2048) & (KSL - 1)], acc);
                        acc = fmaf(c1, buf[(n - Di - 1 + 2048) & (KSL - 1)], acc);
                        acc = fmaf(c2, buf[(n - Di - 2 + 2048) & (KSL - 1)], acc);
                        buf[n & (KSL - 1)] = acc;
                        sig[n] = acc;
                    }
                    asm volatile("bar.sync 1, %0;" :: "r"(nwT) : "memory");
                }
            }
        } else {
            // doubled: y[n] = x[n] + sum fc[j] x[n-Di-j] + sum ser[j] y[n-lag-j]
            // sig stays pristine x; y->sig writes delayed 2 chunks (write
            // region <= base-Cb-1 < min FIR read base-Di-2 since Cb >= Di+2).
            if (tid < nwT) {
                float y0 = 0.f, y1v = 0.f;
                int rounds = (NSMP + Cb - 1) / Cb;
                int base = 0;
                for (int k = 0; k < rounds; k++, base += Cb) {
                    int n = base + tid;
                    float y = 0.f;
                    if (tid < Cb && n < NSMP) {
                        float acc = sig[n];
                        int i0 = n - Di, i1 = n - Di - 1, i2 = n - Di - 2;
                        float v0 = (i0 >= 0) ? sig[i0] : 0.f;
                        float v1 = (i1 >= 0) ? sig[i1] : 0.f;
                        float v2 = (i2 >= 0) ? sig[i2] : 0.f;
                        acc = fmaf(f0c, v0, acc);
                        acc = fmaf(f1c, v1, acc);
                        acc = fmaf(f2c, v2, acc);
                        int p = n - lag;
                        acc = fmaf(c0, buf[(p     + 2048) & (KSL - 1)], acc);
                        acc = fmaf(c1, buf[(p - 1 + 2048) & (KSL - 1)], acc);
                        acc = fmaf(c2, buf[(p - 2 + 2048) & (KSL - 1)], acc);
                        acc = fmaf(c3, buf[(p - 3 + 2048) & (KSL - 1)], acc);
                        acc = fmaf(c4, buf[(p - 4 + 2048) & (KSL - 1)], acc);
                        buf[n & (KSL - 1)] = acc;
                        y = acc;
                    }
                    int wb = base - 2 * Cb + tid;
                    if (tid < Cb && wb >= 0) sig[wb] = y0;
                    y0 = y1v; y1v = y;
                    asm volatile("bar.sync 1, %0;" :: "r"(nwT) : "memory");
                }
                // flush last two chunks' delayed writes
                for (int ff = 0; ff < 2; ff++, base += Cb) {
                    int wb = base - 2 * Cb + tid;
                    if (tid < Cb && wb >= 0 && wb < NSMP) sig[wb] = y0;
                    y0 = y1v; y1v = 0.f;
                }
            }
        }
        __syncthreads();
    }

    // post one-pole LP
    lp_inplace(sig, scan, s_mpost, s_scpost, tid);

    // write string out for the body stage
    float* yout = d_scr + b * NSMP;
    for (int i = tid; i < NSMP; i += NTH) yout[i] = sig[i];
}

// ---------------------------------------------------------------------------
// Body pass A: per (chunk, batch) 1-warp block, lane = band.
// ---------------------------------------------------------------------------
__global__ void bodyA_kernel()
{
    __shared__ float shx[BL];
    int b = blockIdx.y, c = blockIdx.x, tid = threadIdx.x;
    const float* x = d_scr + b * NSMP + c * BL;
    for (int i = tid; i < BL; i += 32) shx[i] = x[i];
    __syncthreads();
    if (tid < NB) {
        float a1 = d_bA1[tid], a2 = d_bA2[tid], b0 = d_bB0[tid];
        float y1 = 0.f, y2 = 0.f;
        #pragma unroll 8
        for (int t = 0; t < BL; t++) {
            float u = fmaf(-a2, y2, b0 * shx[t]);
            float y = fmaf(-a1, y1, u);
            y2 = y1; y1 = y;
        }
        d_carry[b][c][tid] = make_float2(y1, y2);
    }
}

// ---------------------------------------------------------------------------
// Body pass B: parallel affine scan of chunk carries with exact
// (double-computed) level matrices. Exclusive -> d_initS.
// ---------------------------------------------------------------------------
__global__ void bodyB_kernel()
{
    __shared__ float2 s[BC];
    int band = blockIdx.x, b = blockIdx.y, c = threadIdx.x;
    float2 v = d_carry[b][c][band];
    s[c] = v;
    __syncthreads();
    #pragma unroll
    for (int j = 0; j < NLVL; j++) {
        int ofs = 1 << j;
        float q00 = d_Pl[band][j][0], q01 = d_Pl[band][j][1];
        float q10 = d_Pl[band][j][2], q11 = d_Pl[band][j][3];
        float2 pv = (c >= ofs) ? s[c - ofs] : make_float2(0.f, 0.f);
        __syncthreads();
        v.x = fmaf(q00, pv.x, fmaf(q01, pv.y, v.x));
        v.y = fmaf(q10, pv.x, fmaf(q11, pv.y, v.y));
        s[c] = v;
        __syncthreads();
    }
    d_initS[b][c][band] = (c > 0) ? s[c - 1] : make_float2(0.f, 0.f);
}

// ---------------------------------------------------------------------------
// Body pass C: recompute chunks with correct init, weighted band sum.
// ---------------------------------------------------------------------------
__global__ void bodyC_kernel(const float* __restrict__ gains, float* __restrict__ out)
{
    __shared__ float shx[BL];
    __shared__ float tile[BL * 25];   // [t][band], stride 25 (pad)
    __shared__ float shg[NB];
    int b = blockIdx.y, c = blockIdx.x, tid = threadIdx.x;
    const float* x = d_scr + b * NSMP + c * BL;
    for (int i = tid; i < BL; i += 32) shx[i] = x[i];
    if (tid < NB) shg[tid] = gains[tid];
    __syncthreads();

    if (tid < NB) {
        float a1 = d_bA1[tid], a2 = d_bA2[tid], b0 = d_bB0[tid];
        float2 s = d_initS[b][c][tid];
        float y1 = s.x, y2 = s.y;
        #pragma unroll 8
        for (int t = 0; t < BL; t++) {
            float u = fmaf(-a2, y2, b0 * shx[t]);
            float y = fmaf(-a1, y1, u);
            tile[t * 25 + tid] = y;
            y2 = y1; y1 = y;
        }
    }
    __syncthreads();

    for (int t = tid; t < BL; t += 32) {
        float acc = 0.f;
        #pragma unroll
        for (int k = 0; k < NB; k++) acc = fmaf(tile[t * 25 + k], shg[k], acc);
        out[b * NSMP + c * BL + t] = acc;
    }
}

// ---------------------------------------------------------------------------
extern "C" void kernel_launch(void* const* d_in, const int* in_sizes, int n_in,
                              void* d_out, int out_size)
{
    const float* exc   = (const float*)d_in[0];   // [8,1,32768]
    const float* pitch = (const float*)d_in[1];   // [8,1]
    const float* w1    = (const float*)d_in[2];   // [16,1]
    const float* b1    = (const float*)d_in[3];   // [16]
    const float* w2    = (const float*)d_in[4];   // [3,16]
    const float* b2    = (const float*)d_in[5];   // [3]
    const float* eg    = (const float*)d_in[6];   // scalar
    const float* bg    = (const float*)d_in[7];   // [1,24]
    float* out = (float*)d_out;

    int wr = (out_size >= BATCH * NSMP + 3) ? 1 : 0;

    const int smem_fused = (NSMP + KSL + NTH) * (int)sizeof(float);   // ~136 KB
    cudaFuncSetAttribute(fused_kernel,
                         cudaFuncAttributeMaxDynamicSharedMemorySize, smem_fused);

    fused_kernel<<<BATCH, NTH, smem_fused>>>(exc, pitch, w1, b1, w2, b2, eg,
                                             out + BATCH * NSMP, wr);
    bodyA_kernel<<<dim3(BC, BATCH), 32>>>();
    bodyB_kernel<<<dim3(NB, BATCH), BC>>>();
    bodyC_kernel<<<dim3(BC, BATCH), 32>>>(bg, out);
}

// round 7
// speedup vs baseline: 2.1089x; 1.3960x over previous
#include <cuda_runtime.h>
#include <math.h>

// ---------------------------------------------------------------------------
// AcousticGuitarPoC: fused (params + pre-LP + adaptive-doubled KS + post-LP)
// -> bodyA/bodyB/bodyC parallel resonator bank. B=8, N=32768. 4 launches.
// R7: skewed smem signal layout SIDX(n)=n+(n>>7) kills the 32-way bank
// conflict in both LP passes (lane stride 128 floats -> 129 floats).
// ---------------------------------------------------------------------------

#define FS_F   44100.0f
#define PI_F   3.14159265358979323846f
#define NB     24
#define NSMP   32768
#define BATCH  8
#define NTH    256      // fused-kernel threads
#define LCH    128      // LP chunk length (256*128 = 32768)
#define KSL    1024     // KS ring (power of 2)
#define BL     128      // body chunk length
#define BC     256      // body chunk count (256*128 = 32768)
#define NLVL   8        // log2(BC) scan levels

#define SIDX(n) ((n) + ((n) >> 7))          // skewed signal index
#define SIGSZ   (NSMP + (NSMP >> 7))        // 33024 floats

__device__ float  d_bA1[NB], d_bA2[NB], d_bB0[NB];
__device__ float  d_Pl[NB][NLVL][4];          // M^(BL*2^j), double-computed
__device__ float  d_scr[BATCH * NSMP];        // string output for body stage
__device__ float2 d_carry[BATCH][BC][NB];     // body zero-init chunk end states
__device__ float2 d_initS[BATCH][BC][NB];     // body corrected chunk init states

__device__ __forceinline__ float sigm(float x) { return 1.f / (1.f + expf(-x)); }
__device__ __forceinline__ float clampf(float x, float lo, float hi) {
    return fminf(fmaxf(x, lo), hi);
}

__device__ __forceinline__ void mlp_eval(float p,
    const float* __restrict__ w1, const float* __restrict__ b1,
    const float* __restrict__ w2, const float* __restrict__ b2,
    float& lc, float& lm, float& lp)
{
    float m0 = b2[0], m1 = b2[1], m2 = b2[2];
    #pragma unroll
    for (int j = 0; j < 16; j++) {
        float h = fmaxf(fmaf(p, w1[j], b1[j]), 0.f);
        m0 = fmaf(h, w2[j],      m0);
        m1 = fmaf(h, w2[16 + j], m1);
        m2 = fmaf(h, w2[32 + j], m2);
    }
    lc = clampf(m0, -2.0f, 2.5f);
    lm = clampf(m1, -2.5f, 0.0f);
    lp = clampf(m2, -4.0f, 4.0f);
}

// In-place one-pole LP on the SKEWED signal: y[n] = m*y[n-1] + sc*x[n].
// Thread chunk base = tid*129 (conflict-free). Shuffle carry scan.
__device__ void lp_inplace(float* sig, float* ws, float m, float sc, int tid)
{
    int lane = tid & 31, wid = tid >> 5;
    float* x = sig + tid * (LCH + 1);       // skewed chunk start

    float e = 0.f;
    #pragma unroll 8
    for (int k = 0; k < LCH; k++) e = fmaf(m, e, sc * x[k]);

    float f128 = m;
    #pragma unroll
    for (int i = 0; i < 7; i++) f128 *= f128;   // m^128

    // warp-inclusive affine scan: y[c] = f128*y[c-1] + e[c]
    float f = f128;
    #pragma unroll
    for (int ofs = 1; ofs < 32; ofs <<= 1) {
        float v = __shfl_up_sync(0xffffffffu, e, ofs);
        if (lane >= ofs) e = fmaf(f, v, e);
        f *= f;
    }
    // f is now m^4096 = step factor between warp totals

    if (lane == 31) ws[wid] = e;
    __syncthreads();
    if (wid == 0 && lane < 8) {
        float t = ws[lane];
        float g = f;
        #pragma unroll
        for (int ofs = 1; ofs < 8; ofs <<= 1) {
            float v = __shfl_up_sync(0x000000ffu, t, ofs);
            if (lane >= ofs) t = fmaf(g, v, t);
            g *= g;
        }
        ws[lane] = t;
    }
    __syncthreads();

    float carry = (wid > 0) ? ws[wid - 1] : 0.f;
    float lmul = exp2f((float)(lane + 1) * log2f(f128));  // m^(128*(lane+1))
    float Y = fmaf(lmul, carry, e);
    float yp = __shfl_up_sync(0xffffffffu, Y, 1);
    if (lane == 0) yp = carry;
    if (tid == 0)  yp = 0.f;

    #pragma unroll 8
    for (int k = 0; k < LCH; k++) { yp = fmaf(m, yp, sc * x[k]); x[k] = yp; }
    __syncthreads();
}

// ---------------------------------------------------------------------------
// Fused kernel: one block per batch.
// ---------------------------------------------------------------------------
__global__ void fused_kernel(const float* __restrict__ exc,
                             const float* __restrict__ pitch,
                             const float* __restrict__ w1,
                             const float* __restrict__ b1,
                             const float* __restrict__ w2,
                             const float* __restrict__ b2,
                             const float* __restrict__ egain,
                             float* out_tail, int write_scalars)
{
    extern __shared__ float sm[];
    float* sig  = sm;              // [SIGSZ] skewed
    float* buf  = sm + SIGSZ;      // [KSL]
    float* scan = buf + KSL;       // [NTH]

    __shared__ float s_mpre, s_scpre, s_mpost, s_scpost;
    __shared__ float s_ser[5], s_fc[3];
    __shared__ int   s_L, s_Di, s_lag, s_Cb, s_nwT;
    __shared__ float s_lc[BATCH], s_lm[BATCH], s_lp[BATCH];

    int b = blockIdx.x, tid = threadIdx.x;

    if (tid == 0) {
        float p = pitch[b];
        float lc, lm, lp;
        mlp_eval(p, w1, b1, w2, b2, lc, lm, lp);

        float g = 0.999f * sigm(lc);
        float s = sigm(lm);
        float gs  = g * s;
        float g1s = g * (1.f - s);

        float f0    = fmaxf(p, 60.f);
        float mult  = clampf(2.f + 6.f * (f0 - 60.f) / 600.f, 2.f, 8.f);
        float cut   = fminf(2.f * PI_F * f0 * mult / FS_F, PI_F * 0.9f);
        float alpha = 1.f - expf(-cut);
        s_mpre  = 1.f - alpha;
        s_scpre = alpha * egain[0];

        float cutp = fminf(PI_F * sigm(lp), PI_F * 0.99f);
        float ap   = 1.f - expf(-cutp);
        s_mpost  = 1.f - ap;
        s_scpost = ap;

        float D  = clampf(FS_F / f0, 2.f, 735.f);
        float Df = floorf(D);
        int   Di = (int)Df;
        float fr = D - Df;
        s_Di = Di;

        // base loop: y[n] = x[n] + t1[0] y[n-Di] + t1[1] y[n-Di-1] + t1[2] y[n-Di-2]
        float t1[3];
        t1[0] = g1s * (1.f - fr);
        t1[1] = g1s * fr + gs * (1.f - fr);
        t1[2] = gs * fr;

        if (Di - 2 >= 254) {
            s_L   = 0;
            s_lag = Di;
            s_Cb  = min(256, Di - 2);
            for (int k = 0; k < 3; k++) s_ser[k] = t1[k];
            s_ser[3] = 0.f; s_ser[4] = 0.f;
            s_fc[0] = s_fc[1] = s_fc[2] = 0.f;
        } else {
            // L = 1: (1 - C^2) y = (1 + C) x
            float t2[5];
            for (int k = 0; k < 5; k++) t2[k] = 0.f;
            for (int i = 0; i < 3; i++)
                for (int j = 0; j < 3; j++) t2[i + j] = fmaf(t1[i], t1[j], t2[i + j]);
            s_L   = 1;
            s_lag = 2 * Di;
            s_Cb  = min(256, 2 * Di);
            for (int k = 0; k < 5; k++) s_ser[k] = t2[k];
            for (int k = 0; k < 3; k++) s_fc[k]  = t1[k];
        }
        s_nwT = ((s_Cb + 31) >> 5) << 5;
    }

    if (b == 0) {
        if (tid >= 32 && tid < 32 + BATCH) {
            int bb = tid - 32;
            mlp_eval(pitch[bb], w1, b1, w2, b2, s_lc[bb], s_lm[bb], s_lp[bb]);
        }
        if (tid >= 64 && tid < 64 + NB) {
            int band = tid - 64;
            double fc  = 80.0 * exp(log(100.0) * (double)band / 23.0);
            float  fcf = (float)fc;
            float  w   = 2.f * PI_F * fcf / FS_F;
            float  r   = expf(-PI_F * fcf / (10.f * FS_F));
            float  a1  = -2.f * r * cosf(w);
            float  a2  = r * r;
            d_bA1[band] = a1; d_bA2[band] = a2; d_bB0[band] = 1.f - r;
            // scan-level powers M^(128*2^j), all in double (non-normal matrix
            // powers cancel catastrophically in float).
            double ma = -(double)a1, mb = -(double)a2, mc = 1.0, md = 0.0;
            for (int it = 0; it < 7; it++) {
                double na = ma * ma + mb * mc;
                double nb = ma * mb + mb * md;
                double nc = mc * ma + md * mc;
                double nd = mc * mb + md * md;
                ma = na; mb = nb; mc = nc; md = nd;
            }
            for (int j = 0; j < NLVL; j++) {
                d_Pl[band][j][0] = (float)ma; d_Pl[band][j][1] = (float)mb;
                d_Pl[band][j][2] = (float)mc; d_Pl[band][j][3] = (float)md;
                double na = ma * ma + mb * mc;
                double nb = ma * mb + mb * md;
                double nc = mc * ma + md * mc;
                double nd = mc * mb + md * md;
                ma = na; mb = nb; mc = nc; md = nd;
            }
        }
    }
    __syncthreads();

    if (b == 0 && tid == 0 && write_scalars) {
        float sc = 0.f, smm = 0.f, spp = 0.f;
        for (int i = 0; i < BATCH; i++) { sc += s_lc[i]; smm += s_lm[i]; spp += s_lp[i]; }
        out_tail[0] = sc  / (float)BATCH;
        out_tail[1] = smm / (float)BATCH;
        out_tail[2] = spp / (float)BATCH;
    }

    // load excitation (skewed) + zero KS ring
    const float* xin = exc + b * NSMP;
    for (int i = tid; i < NSMP; i += NTH) sig[SIDX(i)] = xin[i];
    for (int i = tid; i < KSL; i += NTH) buf[i] = 0.f;
    __syncthreads();

    // pre one-pole LP
    lp_inplace(sig, scan, s_mpre, s_scpre, tid);

    // ---------------- Karplus-Strong ----------------
    {
        int Di = s_Di, lag = s_lag, Cb = s_Cb, nwT = s_nwT, L = s_L;
        float c0 = s_ser[0], c1 = s_ser[1], c2 = s_ser[2],
              c3 = s_ser[3], c4 = s_ser[4];
        float f0c = s_fc[0], f1c = s_fc[1], f2c = s_fc[2];

        if (L == 0) {
            // plain 3-tap recurrence; named barrier over participating warps
            if (tid < nwT) {
                for (int base = 0; base < NSMP; base += Cb) {
                    int n = base + tid;
                    if (tid < Cb && n < NSMP) {
                        float acc = sig[SIDX(n)];
                        acc = fmaf(c0, buf[(n - Di     + 2048) & (KSL - 1)], acc);
                        acc = fmaf(c1, buf[(n - Di - 1 + 2048) & (KSL - 1)], acc);
                        acc = fmaf(c2, buf[(n - Di - 2 + 2048) & (KSL - 1)], acc);
                        buf[n & (KSL - 1)] = acc;
                        sig[SIDX(n)] = acc;
                    }
                    asm volatile("bar.sync 1, %0;" :: "r"(nwT) : "memory");
                }
            }
        } else {
            // doubled: y[n] = x[n] + sum fc[j] x[n-Di-j] + sum ser[j] y[n-lag-j]
            // sig stays pristine x; y->sig writes delayed 2 chunks (write
            // region <= base-Cb-1 < min FIR read base-Di-2 since Cb >= Di+2).
            if (tid < nwT) {
                float y0 = 0.f, y1v = 0.f;
                int rounds = (NSMP + Cb - 1) / Cb;
                int base = 0;
                for (int k = 0; k < rounds; k++, base += Cb) {
                    int n = base + tid;
                    float y = 0.f;
                    if (tid < Cb && n < NSMP) {
                        float acc = sig[SIDX(n)];
                        int i0 = n - Di, i1 = n - Di - 1, i2 = n - Di - 2;
                        float v0 = (i0 >= 0) ? sig[SIDX(i0)] : 0.f;
                        float v1 = (i1 >= 0) ? sig[SIDX(i1)] : 0.f;
                        float v2 = (i2 >= 0) ? sig[SIDX(i2)] : 0.f;
                        acc = fmaf(f0c, v0, acc);
                        acc = fmaf(f1c, v1, acc);
                        acc = fmaf(f2c, v2, acc);
                        int p = n - lag;
                        acc = fmaf(c0, buf[(p     + 2048) & (KSL - 1)], acc);
                        acc = fmaf(c1, buf[(p - 1 + 2048) & (KSL - 1)], acc);
                        acc = fmaf(c2, buf[(p - 2 + 2048) & (KSL - 1)], acc);
                        acc = fmaf(c3, buf[(p - 3 + 2048) & (KSL - 1)], acc);
                        acc = fmaf(c4, buf[(p - 4 + 2048) & (KSL - 1)], acc);
                        buf[n & (KSL - 1)] = acc;
                        y = acc;
                    }
                    int wb = base - 2 * Cb + tid;
                    if (tid < Cb && wb >= 0) sig[SIDX(wb)] = y0;
                    y0 = y1v; y1v = y;
                    asm volatile("bar.sync 1, %0;" :: "r"(nwT) : "memory");
                }
                // flush last two chunks' delayed writes
                for (int ff = 0; ff < 2; ff++, base += Cb) {
                    int wb = base - 2 * Cb + tid;
                    if (tid < Cb && wb >= 0 && wb < NSMP) sig[SIDX(wb)] = y0;
                    y0 = y1v; y1v = 0.f;
                }
            }
        }
        __syncthreads();
    }

    // post one-pole LP
    lp_inplace(sig, scan, s_mpost, s_scpost, tid);

    // write string out for the body stage (de-skew)
    float* yout = d_scr + b * NSMP;
    for (int i = tid; i < NSMP; i += NTH) yout[i] = sig[SIDX(i)];
}

// ---------------------------------------------------------------------------
// Body pass A: per (chunk, batch) 1-warp block, lane = band.
// ---------------------------------------------------------------------------
__global__ void bodyA_kernel()
{
    __shared__ float shx[BL];
    int b = blockIdx.y, c = blockIdx.x, tid = threadIdx.x;
    const float* x = d_scr + b * NSMP + c * BL;
    for (int i = tid; i < BL; i += 32) shx[i] = x[i];
    __syncthreads();
    if (tid < NB) {
        float a1 = d_bA1[tid], a2 = d_bA2[tid], b0 = d_bB0[tid];
        float y1 = 0.f, y2 = 0.f;
        #pragma unroll 8
        for (int t = 0; t < BL; t++) {
            float u = fmaf(-a2, y2, b0 * shx[t]);
            float y = fmaf(-a1, y1, u);
            y2 = y1; y1 = y;
        }
        d_carry[b][c][tid] = make_float2(y1, y2);
    }
}

// ---------------------------------------------------------------------------
// Body pass B: parallel affine scan of chunk carries with exact
// (double-computed) level matrices. Exclusive -> d_initS.
// ---------------------------------------------------------------------------
__global__ void bodyB_kernel()
{
    __shared__ float2 s[BC];
    int band = blockIdx.x, b = blockIdx.y, c = threadIdx.x;
    float2 v = d_carry[b][c][band];
    s[c] = v;
    __syncthreads();
    #pragma unroll
    for (int j = 0; j < NLVL; j++) {
        int ofs = 1 << j;
        float q00 = d_Pl[band][j][0], q01 = d_Pl[band][j][1];
        float q10 = d_Pl[band][j][2], q11 = d_Pl[band][j][3];
        float2 pv = (c >= ofs) ? s[c - ofs] : make_float2(0.f, 0.f);
        __syncthreads();
        v.x = fmaf(q00, pv.x, fmaf(q01, pv.y, v.x));
        v.y = fmaf(q10, pv.x, fmaf(q11, pv.y, v.y));
        s[c] = v;
        __syncthreads();
    }
    d_initS[b][c][band] = (c > 0) ? s[c - 1] : make_float2(0.f, 0.f);
}

// ---------------------------------------------------------------------------
// Body pass C: recompute chunks with correct init, weighted band sum.
// ---------------------------------------------------------------------------
__global__ void bodyC_kernel(const float* __restrict__ gains, float* __restrict__ out)
{
    __shared__ float shx[BL];
    __shared__ float tile[BL * 25];   // [t][band], stride 25 (pad)
    __shared__ float shg[NB];
    int b = blockIdx.y, c = blockIdx.x, tid = threadIdx.x;
    const float* x = d_scr + b * NSMP + c * BL;
    for (int i = tid; i < BL; i += 32) shx[i] = x[i];
    if (tid < NB) shg[tid] = gains[tid];
    __syncthreads();

    if (tid < NB) {
        float a1 = d_bA1[tid], a2 = d_bA2[tid], b0 = d_bB0[tid];
        float2 s = d_initS[b][c][tid];
        float y1 = s.x, y2 = s.y;
        #pragma unroll 8
        for (int t = 0; t < BL; t++) {
            float u = fmaf(-a2, y2, b0 * shx[t]);
            float y = fmaf(-a1, y1, u);
            tile[t * 25 + tid] = y;
            y2 = y1; y1 = y;
        }
    }
    __syncthreads();

    for (int t = tid; t < BL; t += 32) {
        float acc = 0.f;
        #pragma unroll
        for (int k = 0; k < NB; k++) acc = fmaf(tile[t * 25 + k], shg[k], acc);
        out[b * NSMP + c * BL + t] = acc;
    }
}

// ---------------------------------------------------------------------------
extern "C" void kernel_launch(void* const* d_in, const int* in_sizes, int n_in,
                              void* d_out, int out_size)
{
    const float* exc   = (const float*)d_in[0];   // [8,1,32768]
    const float* pitch = (const float*)d_in[1];   // [8,1]
    const float* w1    = (const float*)d_in[2];   // [16,1]
    const float* b1    = (const float*)d_in[3];   // [16]
    const float* w2    = (const float*)d_in[4];   // [3,16]
    const float* b2    = (const float*)d_in[5];   // [3]
    const float* eg    = (const float*)d_in[6];   // scalar
    const float* bg    = (const float*)d_in[7];   // [1,24]
    float* out = (float*)d_out;

    int wr = (out_size >= BATCH * NSMP + 3) ? 1 : 0;

    const int smem_fused = (SIGSZ + KSL + NTH) * (int)sizeof(float);  // ~137 KB
    cudaFuncSetAttribute(fused_kernel,
                         cudaFuncAttributeMaxDynamicSharedMemorySize, smem_fused);

    fused_kernel<<<BATCH, NTH, smem_fused>>>(exc, pitch, w1, b1, w2, b2, eg,
                                             out + BATCH * NSMP, wr);
    bodyA_kernel<<<dim3(BC, BATCH), 32>>>();
    bodyB_kernel<<<dim3(NB, BATCH), BC>>>();
    bodyC_kernel<<<dim3(BC, BATCH), 32>>>(bg, out);
}